// round 17
// baseline (speedup 1.0000x reference)
#include <cuda_runtime.h>
#include <cstdint>

// Problem constants (fixed shapes from setup_inputs)
#define TT 64
#define BB 4096
#define DD 32
#define HH 5
#define GG 20      // 4*H gates
#define VV 10
#define IN 128

#define BLK 256
#define NCHUNK (BB / BLK)           // 16 b-chunks
#define TGRID (TT / 2)              // 32 (two t per thread: t and t+32)

// gate g is the tanh (cell-candidate) gate iff 10 <= g < 15; others sigmoid.
// Sigmoid rows are pre-scaled by 0.5 so sigma(v) = 0.5*tanh(v') + 0.5 with
// v' the scaled pre-activation (exact power-of-2 scaling).
__device__ __forceinline__ float gate_scale(int g) {
    return (g >= 2 * HH && g < 3 * HH) ? 1.0f : 0.5f;
}

__device__ __forceinline__ float tanh_fast(float v) {
    float r;
    asm("tanh.approx.f32 %0, %1;" : "=f"(r) : "f"(v));
    return r;
}
__device__ __forceinline__ float sigm_pre(float vh) {   // vh = v/2
    return fmaf(0.5f, tanh_fast(vh), 0.5f);
}

// ---------------------------------------------------------------------------
// Single fused kernel. One thread per (b, {t, t+32}), register-interleaved.
// Everything formerly in prep (embedding LUT, h@W_hh+bias, cell gather) is
// computed in-block/in-thread: LUT once per block (cheap), hb per thread
// (100 FMA per layer, shared across the two t-items).
//   blockIdx.x = b-chunk (16), blockIdx.y = t0 (32). 256 threads, 64-reg cap.
// ---------------------------------------------------------------------------
__global__ void __launch_bounds__(BLK, 4)
decoder_kernel(const float* __restrict__ hidden,
               const float* __restrict__ cell,
               const float* __restrict__ dec_x,
               const int*   __restrict__ id1,
               const int*   __restrict__ id2,
               const int*   __restrict__ id3,
               const float* __restrict__ embed,
               const float* __restrict__ W_ih0,
               const float* __restrict__ W_hh0,
               const float* __restrict__ b_ih0,
               const float* __restrict__ b_hh0,
               const float* __restrict__ W_ih1,
               const float* __restrict__ W_hh1,
               const float* __restrict__ b_ih1,
               const float* __restrict__ b_hh1,
               float* __restrict__ out) {
    __shared__ __align__(16) float sWa[GG * DD];        // scaled W_ih0[:,0:32]
    __shared__ __align__(16) float sLut[3 * VV * GG];   // [j][v][g] scaled
    __shared__ __align__(16) float sW1t[HH * GG];       // scaled W_ih1^T [k][g]
    __shared__ __align__(16) float sWh0t[HH * GG];      // scaled W_hh0^T [k][g]
    __shared__ __align__(16) float sWh1t[HH * GG];      // scaled W_hh1^T [k][g]
    __shared__ __align__(16) float sB0[GG];             // scaled b_ih0+b_hh0
    __shared__ __align__(16) float sB1[GG];             // scaled b_ih1+b_hh1
    __shared__ __align__(16) float sOut[2 * BLK * HH];  // output staging

    const int tid = threadIdx.x;

    // ---- cooperative shared fill ----
    for (int i = tid; i < GG * DD; i += BLK) {
        int g = i >> 5, k = i & 31;
        sWa[i] = W_ih0[g * IN + k] * gate_scale(g);
    }
    for (int i = tid; i < HH * GG; i += BLK) {
        int k = i / GG, g = i - k * GG;
        float sc = gate_scale(g);
        sW1t[i]  = W_ih1[g * HH + k] * sc;
        sWh0t[i] = W_hh0[g * HH + k] * sc;
        sWh1t[i] = W_hh1[g * HH + k] * sc;
    }
    for (int i = tid; i < GG; i += BLK) {
        float sc = gate_scale(i);
        sB0[i] = (b_ih0[i] + b_hh0[i]) * sc;
        sB1[i] = (b_ih1[i] + b_hh1[i]) * sc;
    }
    // embedding->gate LUT: 600 entries, 32-dot each (f4 LDG, L1-hot reuse)
    for (int i = tid; i < 3 * VV * GG; i += BLK) {
        int j = i / (VV * GG);
        int r = i - j * (VV * GG);
        int v = r / GG;
        int g = r - v * GG;
        const float4* e4 = (const float4*)(embed + v * DD);
        const float4* w4 = (const float4*)(W_ih0 + g * IN + DD + DD * j);
        float s = 0.0f;
#pragma unroll
        for (int q = 0; q < DD / 4; q++) {
            float4 e = e4[q], w = w4[q];
            s = fmaf(e.x, w.x, fmaf(e.y, w.y,
                fmaf(e.z, w.z, fmaf(e.w, w.w, s))));
        }
        sLut[i] = s * gate_scale(g);
    }
    __syncthreads();

    const int b   = blockIdx.x * BLK + tid;
    const int t0  = blockIdx.y;                 // item 0: t0, item 1: t0+32
    const int tbA = t0 * BB + b;
    const int tbB = (t0 + TGRID) * BB + b;

    // ---- acc[0] = sB0 + W_hh0~ . h0   (h0 dies after this) ----
    float acc[2][GG];
#pragma unroll
    for (int q = 0; q < GG / 4; q++) {
        float4 bv = ((const float4*)sB0)[q];
        acc[0][4 * q + 0] = bv.x;
        acc[0][4 * q + 1] = bv.y;
        acc[0][4 * q + 2] = bv.z;
        acc[0][4 * q + 3] = bv.w;
    }
#pragma unroll
    for (int k = 0; k < HH; k++) {
        float hv = hidden[b * HH + k];
        const float4* wp = (const float4*)(sWh0t + k * GG);
#pragma unroll
        for (int q = 0; q < GG / 4; q++) {
            float4 w = wp[q];
            acc[0][4 * q + 0] = fmaf(hv, w.x, acc[0][4 * q + 0]);
            acc[0][4 * q + 1] = fmaf(hv, w.y, acc[0][4 * q + 1]);
            acc[0][4 * q + 2] = fmaf(hv, w.z, acc[0][4 * q + 2]);
            acc[0][4 * q + 3] = fmaf(hv, w.w, acc[0][4 * q + 3]);
        }
    }
#pragma unroll
    for (int g = 0; g < GG; g++) acc[1][g] = acc[0][g];

    // ---- embedding LUT adds per item (f4 over g) ----
#pragma unroll
    for (int it = 0; it < 2; it++) {
        const int tb = (it == 0) ? tbA : tbB;
        const int i1 = id1[tb], i2 = id2[tb], i3 = id3[tb];
        const float4* l1 = (const float4*)(sLut + (0 * VV + i1) * GG);
        const float4* l2 = (const float4*)(sLut + (1 * VV + i2) * GG);
        const float4* l3 = (const float4*)(sLut + (2 * VV + i3) * GG);
#pragma unroll
        for (int q = 0; q < GG / 4; q++) {
            float4 a = l1[q], c = l2[q], d = l3[q];
            acc[it][4 * q + 0] += a.x + c.x + d.x;
            acc[it][4 * q + 1] += a.y + c.y + d.y;
            acc[it][4 * q + 2] += a.z + c.z + d.z;
            acc[it][4 * q + 3] += a.w + c.w + d.w;
        }
    }

    // ---- dual-t GEMM: each weight LDS.128 feeds both items (8 FMA/load) ----
    {
        const float4* xpA = (const float4*)(dec_x + (size_t)tbA * DD);
        const float4* xpB = (const float4*)(dec_x + (size_t)tbB * DD);
#pragma unroll
        for (int q = 0; q < DD / 4; q++) {
            float4 xa = xpA[q];
            float4 xb = xpB[q];
            const float4* wp = (const float4*)sWa + q;   // stride DD/4 per gate
#pragma unroll
            for (int g = 0; g < GG; g++) {
                float4 w = wp[g * (DD / 4)];
                acc[0][g] = fmaf(xa.x, w.x, fmaf(xa.y, w.y,
                            fmaf(xa.z, w.z, fmaf(xa.w, w.w, acc[0][g]))));
                acc[1][g] = fmaf(xb.x, w.x, fmaf(xb.y, w.y,
                            fmaf(xb.z, w.z, fmaf(xb.w, w.w, acc[1][g]))));
            }
        }
    }

    // ---- LSTM cell 0 for both items (c0 loaded here, dies after) ----
    float h1[2][HH];
#pragma unroll
    for (int k = 0; k < HH; k++) {
        float cc = cell[b * HH + k];
#pragma unroll
        for (int it = 0; it < 2; it++) {
            float ig = sigm_pre(acc[it][k]);
            float fg = sigm_pre(acc[it][HH + k]);
            float gg = tanh_fast(acc[it][2 * HH + k]);
            float og = sigm_pre(acc[it][3 * HH + k]);
            float c  = fmaf(fg, cc, ig * gg);
            h1[it][k] = og * tanh_fast(c);
        }
    }

    // ---- a1[0] = sB1 + W_hh1~ . hinit1  (hinit1 dies), copy, += W1t.h1 ----
    float a1[2][GG];
#pragma unroll
    for (int q = 0; q < GG / 4; q++) {
        float4 bv = ((const float4*)sB1)[q];
        a1[0][4 * q + 0] = bv.x;
        a1[0][4 * q + 1] = bv.y;
        a1[0][4 * q + 2] = bv.z;
        a1[0][4 * q + 3] = bv.w;
    }
#pragma unroll
    for (int k = 0; k < HH; k++) {
        float hv = hidden[BB * HH + b * HH + k];
        const float4* wp = (const float4*)(sWh1t + k * GG);
#pragma unroll
        for (int q = 0; q < GG / 4; q++) {
            float4 w = wp[q];
            a1[0][4 * q + 0] = fmaf(hv, w.x, a1[0][4 * q + 0]);
            a1[0][4 * q + 1] = fmaf(hv, w.y, a1[0][4 * q + 1]);
            a1[0][4 * q + 2] = fmaf(hv, w.z, a1[0][4 * q + 2]);
            a1[0][4 * q + 3] = fmaf(hv, w.w, a1[0][4 * q + 3]);
        }
    }
#pragma unroll
    for (int g = 0; g < GG; g++) a1[1][g] = a1[0][g];

#pragma unroll
    for (int k = 0; k < HH; k++) {
        const float4* wp = (const float4*)(sW1t + k * GG);
#pragma unroll
        for (int q = 0; q < GG / 4; q++) {
            float4 w = wp[q];
#pragma unroll
            for (int it = 0; it < 2; it++) {
                float hv = h1[it][k];
                a1[it][4 * q + 0] = fmaf(hv, w.x, a1[it][4 * q + 0]);
                a1[it][4 * q + 1] = fmaf(hv, w.y, a1[it][4 * q + 1]);
                a1[it][4 * q + 2] = fmaf(hv, w.z, a1[it][4 * q + 2]);
                a1[it][4 * q + 3] = fmaf(hv, w.w, a1[it][4 * q + 3]);
            }
        }
    }

    // ---- LSTM cell 1 for both items -> staged output ----
#pragma unroll
    for (int k = 0; k < HH; k++) {
        float cc = cell[BB * HH + b * HH + k];
#pragma unroll
        for (int it = 0; it < 2; it++) {
            float ig = sigm_pre(a1[it][k]);
            float fg = sigm_pre(a1[it][HH + k]);
            float gg = tanh_fast(a1[it][2 * HH + k]);
            float og = sigm_pre(a1[it][3 * HH + k]);
            float c  = fmaf(fg, cc, ig * gg);
            sOut[it * BLK * HH + tid * HH + k] = og * tanh_fast(c);
        }
    }
    __syncthreads();

    // ---- coalesced store of both [256, 5] output slabs ----
    {
        float* obA = out + (size_t)t0 * BB * HH + (size_t)blockIdx.x * BLK * HH;
        float* obB = out + (size_t)(t0 + TGRID) * BB * HH
                         + (size_t)blockIdx.x * BLK * HH;
        for (int i = tid; i < BLK * HH; i += BLK) {
            obA[i] = sOut[i];
            obB[i] = sOut[BLK * HH + i];
        }
    }
}

// ---------------------------------------------------------------------------
// Launch — single fused kernel.
// Input order: 0 horizon, 1 hidden, 2 cell, 3 dec_x, 4 mote_id_cat,
// 5 fault_type_cat, 6 mote_fault_cat, 7 mote_embed, 8 W_ih0, 9 W_hh0,
// 10 b_ih0, 11 b_hh0, 12 W_ih1, 13 W_hh1, 14 b_ih1, 15 b_hh1
// ---------------------------------------------------------------------------
extern "C" void kernel_launch(void* const* d_in, const int* in_sizes, int n_in,
                              void* d_out, int out_size) {
    const float* hidden = (const float*)d_in[1];
    const float* cell   = (const float*)d_in[2];
    const float* dec_x  = (const float*)d_in[3];
    const int*   id1    = (const int*)d_in[4];
    const int*   id2    = (const int*)d_in[5];
    const int*   id3    = (const int*)d_in[6];
    const float* embed  = (const float*)d_in[7];
    const float* W_ih0  = (const float*)d_in[8];
    const float* W_hh0  = (const float*)d_in[9];
    const float* b_ih0  = (const float*)d_in[10];
    const float* b_hh0  = (const float*)d_in[11];
    const float* W_ih1  = (const float*)d_in[12];
    const float* W_hh1  = (const float*)d_in[13];
    const float* b_ih1  = (const float*)d_in[14];
    const float* b_hh1  = (const float*)d_in[15];
    float* out = (float*)d_out;

    dim3 grid(NCHUNK, TGRID);
    decoder_kernel<<<grid, BLK>>>(hidden, cell, dec_x, id1, id2, id3, embed,
                                  W_ih0, W_hh0, b_ih0, b_hh0,
                                  W_ih1, W_hh1, b_ih1, b_hh1, out);
}